// round 1
// baseline (speedup 1.0000x reference)
#include <cuda_runtime.h>

// ---------------------------------------------------------------------------
// 3-layer GCN: out = GCNconv3( relu(GCNconv2( relu(GCNconv1(x)) )) )
// GCNconv(h) = D^{-1/2} (A + I) D^{-1/2} (h @ W) + b
//
// Strategy:
//   1) Build CSR by destination (count -> scan -> scatter), int atomics only.
//   2) dis[i] = rsqrt(deg_in[i] + 1)   (self-loop included)
//   3) Per layer: dense fp32 tiled GEMM (transform first), then warp-per-node
//      register aggregation over CSR (gathers are L2-resident, no fp atomics).
// ---------------------------------------------------------------------------

#define NN 100000
#define NE 1600000
#define IN_C 256
#define H1C 128
#define H2C 64
#define OUTC 32

// scratch (device globals: allocation-free)
__device__ int    g_cnt[NN];
__device__ int    g_cursor[NN];
__device__ int    g_off[NN];
__device__ int    g_bsum[128];
__device__ int    g_boff[128];
__device__ float  g_dis[NN];
__device__ int    g_esrc[NE];
__device__ float  g_enorm[NE];
__device__ float4 g_h4[(size_t)NN * 32];   // up to 128 floats/node
__device__ float4 g_a4[(size_t)NN * 32];

// ---------------------------------------------------------------------------
// graph preprocessing
// ---------------------------------------------------------------------------
__global__ void k_zero(int n) {
    int i = blockIdx.x * blockDim.x + threadIdx.x;
    if (i < n) { g_cnt[i] = 0; g_cursor[i] = 0; }
}

__global__ void k_count(const int* __restrict__ col, int e_cnt) {
    int e = blockIdx.x * blockDim.x + threadIdx.x;
    if (e < e_cnt) atomicAdd(&g_cnt[col[e]], 1);
}

__global__ void k_dis(int n) {
    int i = blockIdx.x * blockDim.x + threadIdx.x;
    if (i < n) g_dis[i] = rsqrtf((float)g_cnt[i] + 1.0f);
}

__global__ void k_scan1(int n) {
    __shared__ int s[1024];
    int i = blockIdx.x * 1024 + threadIdx.x;
    int v = (i < n) ? g_cnt[i] : 0;
    s[threadIdx.x] = v;
    __syncthreads();
    #pragma unroll
    for (int off = 1; off < 1024; off <<= 1) {
        int t = (threadIdx.x >= off) ? s[threadIdx.x - off] : 0;
        __syncthreads();
        s[threadIdx.x] += t;
        __syncthreads();
    }
    if (i < n) g_off[i] = s[threadIdx.x];          // inclusive for now
    if (threadIdx.x == 1023) g_bsum[blockIdx.x] = s[1023];
}

__global__ void k_scan2(int nb) {
    if (blockIdx.x == 0 && threadIdx.x == 0) {
        int run = 0;
        for (int b = 0; b < nb; b++) { g_boff[b] = run; run += g_bsum[b]; }
    }
}

__global__ void k_scan3(int n) {
    int i = blockIdx.x * blockDim.x + threadIdx.x;
    if (i < n) g_off[i] = g_off[i] - g_cnt[i] + g_boff[i >> 10];  // exclusive
}

__global__ void k_scatter(const int* __restrict__ row, const int* __restrict__ col, int e_cnt) {
    int e = blockIdx.x * blockDim.x + threadIdx.x;
    if (e >= e_cnt) return;
    int r = row[e], c = col[e];
    int pos = g_off[c] + atomicAdd(&g_cursor[c], 1);
    g_esrc[pos]  = r;
    g_enorm[pos] = g_dis[r] * g_dis[c];
}

// ---------------------------------------------------------------------------
// dense GEMM:  C[M,N] = A[M,K] @ W[K,N]   (fp32, tiled SIMT)
// ---------------------------------------------------------------------------
template <int N, int K>
__launch_bounds__(128)
__global__ void k_gemm(const float* __restrict__ A, const float* __restrict__ W,
                       float* __restrict__ C, int M) {
    constexpr int BM = 64, BK = 32;
    constexpr int TN = (N >= 128) ? 8 : 4;
    constexpr int TM = (N == 32) ? 4 : 8;
    constexpr int TX = N / TN;       // 16 / 16 / 8
    constexpr int TY = BM / TM;      //  8 /  8 / 16
    static_assert(TX * TY == 128, "block must be 128 threads");

    __shared__ float As[BK][BM + 4];
    __shared__ float Ws[BK][N];

    int tid = threadIdx.x;
    int tx = tid % TX, ty = tid / TX;
    int m0 = blockIdx.x * BM;

    float acc[TM][TN];
    #pragma unroll
    for (int i = 0; i < TM; i++)
        #pragma unroll
        for (int j = 0; j < TN; j++) acc[i][j] = 0.0f;

    for (int k0 = 0; k0 < K; k0 += BK) {
        // A tile: 64 rows x 32 cols = 512 float4 (transpose into As[k][m])
        #pragma unroll
        for (int i = 0; i < 4; i++) {
            int idx = tid + i * 128;
            int r = idx >> 3;       // row within tile
            int c4 = idx & 7;       // float4 within row
            int m = m0 + r;
            float4 v = make_float4(0.f, 0.f, 0.f, 0.f);
            if (m < M)
                v = *reinterpret_cast<const float4*>(A + (size_t)m * K + k0 + c4 * 4);
            As[c4 * 4 + 0][r] = v.x;
            As[c4 * 4 + 1][r] = v.y;
            As[c4 * 4 + 2][r] = v.z;
            As[c4 * 4 + 3][r] = v.w;
        }
        // W tile: 32 x N floats, row-major
        constexpr int NW4 = N / 4;
        constexpr int TOT4 = BK * NW4;
        #pragma unroll
        for (int i = 0; i < TOT4 / 128; i++) {
            int idx = tid + i * 128;
            int r = idx / NW4, c4 = idx % NW4;
            float4 v = *reinterpret_cast<const float4*>(W + (size_t)(k0 + r) * N + c4 * 4);
            *reinterpret_cast<float4*>(&Ws[r][c4 * 4]) = v;
        }
        __syncthreads();

        #pragma unroll
        for (int k = 0; k < BK; k++) {
            float a[TM], b[TN];
            #pragma unroll
            for (int i = 0; i < TM; i++) a[i] = As[k][ty * TM + i];
            #pragma unroll
            for (int j = 0; j < TN; j++) b[j] = Ws[k][tx * TN + j];
            #pragma unroll
            for (int i = 0; i < TM; i++)
                #pragma unroll
                for (int j = 0; j < TN; j++)
                    acc[i][j] += a[i] * b[j];
        }
        __syncthreads();
    }

    #pragma unroll
    for (int i = 0; i < TM; i++) {
        int m = m0 + ty * TM + i;
        if (m < M) {
            #pragma unroll
            for (int j = 0; j < TN; j += 4) {
                float4 v = make_float4(acc[i][j], acc[i][j + 1], acc[i][j + 2], acc[i][j + 3]);
                *reinterpret_cast<float4*>(C + (size_t)m * N + tx * TN + j) = v;
            }
        }
    }
}

// ---------------------------------------------------------------------------
// aggregation: out[c] = sum_{e: col=c} norm_e * h[row_e] + dis[c]^2*h[c] + bias
// one warp per node; lane holds F/32 contiguous features in registers.
// ---------------------------------------------------------------------------
template <int VEC>
__device__ __forceinline__ void loadv(float* d, const float* __restrict__ p) {
    if constexpr (VEC == 4) {
        float4 t = __ldg(reinterpret_cast<const float4*>(p));
        d[0] = t.x; d[1] = t.y; d[2] = t.z; d[3] = t.w;
    } else if constexpr (VEC == 2) {
        float2 t = __ldg(reinterpret_cast<const float2*>(p));
        d[0] = t.x; d[1] = t.y;
    } else {
        d[0] = __ldg(p);
    }
}

template <int F, bool RELU>
__launch_bounds__(256)
__global__ void k_agg(const float* __restrict__ h, const float* __restrict__ bias,
                      float* __restrict__ out) {
    constexpr int VEC = F / 32;
    int node = (blockIdx.x * blockDim.x + threadIdx.x) >> 5;
    int lane = threadIdx.x & 31;
    if (node >= NN) return;

    float acc[VEC];
    // self-loop: norm = dis^2
    {
        float d = g_dis[node];
        float ns = d * d;
        float t[VEC];
        loadv<VEC>(t, h + (size_t)node * F + lane * VEC);
        #pragma unroll
        for (int v = 0; v < VEC; v++) acc[v] = ns * t[v];
    }

    int start = g_off[node];
    int cnt   = g_cnt[node];
    int e = start, end = start + cnt;

    for (; e + 4 <= end; e += 4) {
        int   s0 = g_esrc[e],   s1 = g_esrc[e + 1],   s2 = g_esrc[e + 2],   s3 = g_esrc[e + 3];
        float n0 = g_enorm[e],  n1 = g_enorm[e + 1],  n2 = g_enorm[e + 2],  n3 = g_enorm[e + 3];
        float t0[VEC], t1[VEC], t2[VEC], t3[VEC];
        loadv<VEC>(t0, h + (size_t)s0 * F + lane * VEC);
        loadv<VEC>(t1, h + (size_t)s1 * F + lane * VEC);
        loadv<VEC>(t2, h + (size_t)s2 * F + lane * VEC);
        loadv<VEC>(t3, h + (size_t)s3 * F + lane * VEC);
        #pragma unroll
        for (int v = 0; v < VEC; v++) {
            acc[v] += n0 * t0[v];
            acc[v] += n1 * t1[v];
            acc[v] += n2 * t2[v];
            acc[v] += n3 * t3[v];
        }
    }
    for (; e < end; e++) {
        int s = g_esrc[e];
        float nm = g_enorm[e];
        float t[VEC];
        loadv<VEC>(t, h + (size_t)s * F + lane * VEC);
        #pragma unroll
        for (int v = 0; v < VEC; v++) acc[v] += nm * t[v];
    }

    // bias (+relu) + store
    float res[VEC];
    #pragma unroll
    for (int v = 0; v < VEC; v++) {
        float r = acc[v] + bias[lane * VEC + v];
        if (RELU) r = fmaxf(r, 0.0f);
        res[v] = r;
    }
    float* op = out + (size_t)node * F + lane * VEC;
    if constexpr (VEC == 4)      *reinterpret_cast<float4*>(op) = make_float4(res[0], res[1], res[2], res[3]);
    else if constexpr (VEC == 2) *reinterpret_cast<float2*>(op) = make_float2(res[0], res[1]);
    else                         *op = res[0];
}

// ---------------------------------------------------------------------------
extern "C" void kernel_launch(void* const* d_in, const int* in_sizes, int n_in,
                              void* d_out, int out_size) {
    const float* x  = (const float*)d_in[0];
    const int*   ei = (const int*)d_in[1];
    const float* W1 = (const float*)d_in[2];
    const float* b1 = (const float*)d_in[3];
    const float* W2 = (const float*)d_in[4];
    const float* b2 = (const float*)d_in[5];
    const float* W3 = (const float*)d_in[6];
    const float* b3 = (const float*)d_in[7];

    int M = in_sizes[0] / IN_C;   // 100000
    int E = in_sizes[1] / 2;      // 1600000
    const int* row = ei;          // sources
    const int* col = ei + E;      // targets
    float* out = (float*)d_out;

    float *gh, *ga;
    cudaGetSymbolAddress((void**)&gh, g_h4);
    cudaGetSymbolAddress((void**)&ga, g_a4);

    int nb1024 = (M + 1023) / 1024;

    // --- graph preprocessing: CSR by destination + symmetric norm ---
    k_zero   <<<(M + 255) / 256, 256>>>(M);
    k_count  <<<(E + 255) / 256, 256>>>(col, E);
    k_dis    <<<(M + 255) / 256, 256>>>(M);
    k_scan1  <<<nb1024, 1024>>>(M);
    k_scan2  <<<1, 32>>>(nb1024);
    k_scan3  <<<(M + 255) / 256, 256>>>(M);
    k_scatter<<<(E + 255) / 256, 256>>>(row, col, E);

    int aggBlocks = (M + 7) / 8;   // 8 warps per 256-thread block, warp/node

    // --- layer 1: 256 -> 128, relu ---
    k_gemm<H1C, IN_C><<<(M + 63) / 64, 128>>>(x, W1, gh, M);
    k_agg<H1C, true><<<aggBlocks, 256>>>(gh, b1, ga);

    // --- layer 2: 128 -> 64, relu ---
    k_gemm<H2C, H1C><<<(M + 63) / 64, 128>>>(ga, W2, gh, M);
    k_agg<H2C, true><<<aggBlocks, 256>>>(gh, b2, ga);

    // --- layer 3: 64 -> 32, no relu ---
    k_gemm<OUTC, H2C><<<(M + 63) / 64, 128>>>(ga, W3, gh, M);
    k_agg<OUTC, false><<<aggBlocks, 256>>>(gh, b3, out);
}

// round 2
// speedup vs baseline: 1.1422x; 1.1422x over previous
#include <cuda_runtime.h>

// ---------------------------------------------------------------------------
// 3-layer GCN. R2: GEMMs moved to tensor cores (mma.sync tf32, 3x-split for
// fp32-grade accuracy). CSR build + warp-per-node aggregation unchanged.
// ---------------------------------------------------------------------------

#define NN 100000
#define NE 1600000
#define IN_C 256
#define H1C 128
#define H2C 64
#define OUTC 32

__device__ int    g_cnt[NN];
__device__ int    g_cursor[NN];
__device__ int    g_off[NN];
__device__ int    g_bsum[128];
__device__ int    g_boff[128];
__device__ float  g_dis[NN];
__device__ int    g_esrc[NE];
__device__ float  g_enorm[NE];
__device__ float4 g_h4[(size_t)NN * 32];
__device__ float4 g_a4[(size_t)NN * 32];

// ---------------------------------------------------------------------------
// graph preprocessing
// ---------------------------------------------------------------------------
__global__ void k_zero(int n) {
    int i = blockIdx.x * blockDim.x + threadIdx.x;
    if (i < n) { g_cnt[i] = 0; g_cursor[i] = 0; }
}

__global__ void k_count(const int* __restrict__ col, int e_cnt) {
    int e = blockIdx.x * blockDim.x + threadIdx.x;
    if (e < e_cnt) atomicAdd(&g_cnt[col[e]], 1);
}

__global__ void k_dis(int n) {
    int i = blockIdx.x * blockDim.x + threadIdx.x;
    if (i < n) g_dis[i] = rsqrtf((float)g_cnt[i] + 1.0f);
}

__global__ void k_scan1(int n) {
    __shared__ int s[1024];
    int i = blockIdx.x * 1024 + threadIdx.x;
    int v = (i < n) ? g_cnt[i] : 0;
    s[threadIdx.x] = v;
    __syncthreads();
    #pragma unroll
    for (int off = 1; off < 1024; off <<= 1) {
        int t = (threadIdx.x >= off) ? s[threadIdx.x - off] : 0;
        __syncthreads();
        s[threadIdx.x] += t;
        __syncthreads();
    }
    if (i < n) g_off[i] = s[threadIdx.x];
    if (threadIdx.x == 1023) g_bsum[blockIdx.x] = s[1023];
}

__global__ void k_scan2(int nb) {
    if (blockIdx.x == 0 && threadIdx.x == 0) {
        int run = 0;
        for (int b = 0; b < nb; b++) { g_boff[b] = run; run += g_bsum[b]; }
    }
}

__global__ void k_scan3(int n) {
    int i = blockIdx.x * blockDim.x + threadIdx.x;
    if (i < n) g_off[i] = g_off[i] - g_cnt[i] + g_boff[i >> 10];
}

__global__ void k_scatter(const int* __restrict__ row, const int* __restrict__ col, int e_cnt) {
    int e = blockIdx.x * blockDim.x + threadIdx.x;
    if (e >= e_cnt) return;
    int r = row[e], c = col[e];
    int pos = g_off[c] + atomicAdd(&g_cursor[c], 1);
    g_esrc[pos]  = r;
    g_enorm[pos] = g_dis[r] * g_dis[c];
}

// ---------------------------------------------------------------------------
// tensor-core GEMM:  C[M,N] = A[M,K] @ W[K,N]  (tf32 3x-split, fp32 accuracy)
// ---------------------------------------------------------------------------
__device__ __forceinline__ unsigned f2tf(float f) {
    unsigned r;
    asm("cvt.rna.tf32.f32 %0, %1;" : "=r"(r) : "f"(f));
    return r;
}

__device__ __forceinline__ void mma_tf32(float* c, const unsigned* a, const unsigned* b) {
    asm volatile(
        "mma.sync.aligned.m16n8k8.row.col.f32.tf32.tf32.f32 "
        "{%0,%1,%2,%3},{%4,%5,%6,%7},{%8,%9},{%0,%1,%2,%3};"
        : "+f"(c[0]), "+f"(c[1]), "+f"(c[2]), "+f"(c[3])
        : "r"(a[0]), "r"(a[1]), "r"(a[2]), "r"(a[3]), "r"(b[0]), "r"(b[1]));
}

template <int N, int K>
__launch_bounds__(256)
__global__ void k_gemm_tc(const float* __restrict__ A, const float* __restrict__ W,
                          float* __restrict__ C, int M) {
    constexpr int BM = 128, BK = 32;
    constexpr int WARPS_M = 4, WARPS_N = 2;
    constexpr int WM = BM / WARPS_M;   // 32
    constexpr int WN = N / WARPS_N;    // 64 / 32 / 16
    constexpr int MT = WM / 16;        // 2
    constexpr int NT = WN / 8;         // 8 / 4 / 2
    constexpr int ASTRIDE = BK + 4;    // 36 floats -> conflict-free frag loads
    constexpr int BSTRIDE = N + 4;

    __shared__ float As[BM * ASTRIDE];
    __shared__ float Ws[BK * BSTRIDE];

    int tid = threadIdx.x;
    int lane = tid & 31, warp = tid >> 5;
    int wm = (warp % WARPS_M) * WM;
    int wn = (warp / WARPS_M) * WN;
    int m0 = blockIdx.x * BM;
    int g = lane >> 2, tg = lane & 3;

    float acc[MT][NT][4] = {};

    for (int k0 = 0; k0 < K; k0 += BK) {
        // A tile: 128x32 fp32 = 1024 float4, 4 per thread
        #pragma unroll
        for (int i = 0; i < 4; i++) {
            int idx = tid + i * 256;
            int r = idx >> 3, c4 = idx & 7;
            int m = m0 + r;
            float4 v = make_float4(0.f, 0.f, 0.f, 0.f);
            if (m < M)
                v = *reinterpret_cast<const float4*>(A + (size_t)m * K + k0 + c4 * 4);
            *reinterpret_cast<float4*>(As + r * ASTRIDE + c4 * 4) = v;
        }
        // W tile: 32xN fp32
        constexpr int BTOT4 = BK * N / 4;
        #pragma unroll
        for (int i = 0; i < BTOT4 / 256; i++) {
            int idx = tid + i * 256;
            int r = idx / (N / 4), c4 = idx % (N / 4);
            float4 v = *reinterpret_cast<const float4*>(W + (size_t)(k0 + r) * N + c4 * 4);
            *reinterpret_cast<float4*>(Ws + r * BSTRIDE + c4 * 4) = v;
        }
        __syncthreads();

        #pragma unroll
        for (int kk = 0; kk < BK; kk += 8) {
            unsigned ahi[MT][4], alo[MT][4];
            #pragma unroll
            for (int mt = 0; mt < MT; mt++) {
                #pragma unroll
                for (int j = 0; j < 4; j++) {
                    int row = wm + mt * 16 + g + (j & 1) * 8;
                    int col = kk + tg + (j >> 1) * 4;
                    float a = As[row * ASTRIDE + col];
                    unsigned h = f2tf(a);
                    ahi[mt][j] = h;
                    alo[mt][j] = f2tf(a - __uint_as_float(h));
                }
            }
            #pragma unroll
            for (int nt = 0; nt < NT; nt++) {
                unsigned bhi[2], blo[2];
                #pragma unroll
                for (int j = 0; j < 2; j++) {
                    int kr = kk + tg + j * 4;
                    int col = wn + nt * 8 + g;
                    float b = Ws[kr * BSTRIDE + col];
                    unsigned h = f2tf(b);
                    bhi[j] = h;
                    blo[j] = f2tf(b - __uint_as_float(h));
                }
                #pragma unroll
                for (int mt = 0; mt < MT; mt++) {
                    mma_tf32(acc[mt][nt], ahi[mt], bhi);
                    mma_tf32(acc[mt][nt], ahi[mt], blo);
                    mma_tf32(acc[mt][nt], alo[mt], bhi);
                }
            }
        }
        __syncthreads();
    }

    // store: c0,c1 at (row, 2tg..2tg+1), c2,c3 at (row+8, same)
    #pragma unroll
    for (int mt = 0; mt < MT; mt++) {
        #pragma unroll
        for (int nt = 0; nt < NT; nt++) {
            int row0 = m0 + wm + mt * 16 + g;
            int col = wn + nt * 8 + 2 * tg;
            if (row0 < M)
                *reinterpret_cast<float2*>(C + (size_t)row0 * N + col) =
                    make_float2(acc[mt][nt][0], acc[mt][nt][1]);
            int row1 = row0 + 8;
            if (row1 < M)
                *reinterpret_cast<float2*>(C + (size_t)row1 * N + col) =
                    make_float2(acc[mt][nt][2], acc[mt][nt][3]);
        }
    }
}

// ---------------------------------------------------------------------------
// aggregation: warp per node, register accumulation over CSR
// ---------------------------------------------------------------------------
template <int VEC>
__device__ __forceinline__ void loadv(float* d, const float* __restrict__ p) {
    if constexpr (VEC == 4) {
        float4 t = __ldg(reinterpret_cast<const float4*>(p));
        d[0] = t.x; d[1] = t.y; d[2] = t.z; d[3] = t.w;
    } else if constexpr (VEC == 2) {
        float2 t = __ldg(reinterpret_cast<const float2*>(p));
        d[0] = t.x; d[1] = t.y;
    } else {
        d[0] = __ldg(p);
    }
}

template <int F, bool RELU>
__launch_bounds__(256)
__global__ void k_agg(const float* __restrict__ h, const float* __restrict__ bias,
                      float* __restrict__ out) {
    constexpr int VEC = F / 32;
    int node = (blockIdx.x * blockDim.x + threadIdx.x) >> 5;
    int lane = threadIdx.x & 31;
    if (node >= NN) return;

    float acc[VEC];
    {
        float d = g_dis[node];
        float ns = d * d;
        float t[VEC];
        loadv<VEC>(t, h + (size_t)node * F + lane * VEC);
        #pragma unroll
        for (int v = 0; v < VEC; v++) acc[v] = ns * t[v];
    }

    int start = g_off[node];
    int cnt   = g_cnt[node];
    int e = start, end = start + cnt;

    for (; e + 4 <= end; e += 4) {
        int   s0 = g_esrc[e],   s1 = g_esrc[e + 1],   s2 = g_esrc[e + 2],   s3 = g_esrc[e + 3];
        float n0 = g_enorm[e],  n1 = g_enorm[e + 1],  n2 = g_enorm[e + 2],  n3 = g_enorm[e + 3];
        float t0[VEC], t1[VEC], t2[VEC], t3[VEC];
        loadv<VEC>(t0, h + (size_t)s0 * F + lane * VEC);
        loadv<VEC>(t1, h + (size_t)s1 * F + lane * VEC);
        loadv<VEC>(t2, h + (size_t)s2 * F + lane * VEC);
        loadv<VEC>(t3, h + (size_t)s3 * F + lane * VEC);
        #pragma unroll
        for (int v = 0; v < VEC; v++) {
            acc[v] += n0 * t0[v];
            acc[v] += n1 * t1[v];
            acc[v] += n2 * t2[v];
            acc[v] += n3 * t3[v];
        }
    }
    for (; e < end; e++) {
        int s = g_esrc[e];
        float nm = g_enorm[e];
        float t[VEC];
        loadv<VEC>(t, h + (size_t)s * F + lane * VEC);
        #pragma unroll
        for (int v = 0; v < VEC; v++) acc[v] += nm * t[v];
    }

    float res[VEC];
    #pragma unroll
    for (int v = 0; v < VEC; v++) {
        float r = acc[v] + bias[lane * VEC + v];
        if (RELU) r = fmaxf(r, 0.0f);
        res[v] = r;
    }
    float* op = out + (size_t)node * F + lane * VEC;
    if constexpr (VEC == 4)      *reinterpret_cast<float4*>(op) = make_float4(res[0], res[1], res[2], res[3]);
    else if constexpr (VEC == 2) *reinterpret_cast<float2*>(op) = make_float2(res[0], res[1]);
    else                         *op = res[0];
}

// ---------------------------------------------------------------------------
extern "C" void kernel_launch(void* const* d_in, const int* in_sizes, int n_in,
                              void* d_out, int out_size) {
    const float* x  = (const float*)d_in[0];
    const int*   ei = (const int*)d_in[1];
    const float* W1 = (const float*)d_in[2];
    const float* b1 = (const float*)d_in[3];
    const float* W2 = (const float*)d_in[4];
    const float* b2 = (const float*)d_in[5];
    const float* W3 = (const float*)d_in[6];
    const float* b3 = (const float*)d_in[7];

    int M = in_sizes[0] / IN_C;   // 100000
    int E = in_sizes[1] / 2;      // 1600000
    const int* row = ei;          // sources
    const int* col = ei + E;      // targets
    float* out = (float*)d_out;

    float *gh, *ga;
    cudaGetSymbolAddress((void**)&gh, g_h4);
    cudaGetSymbolAddress((void**)&ga, g_a4);

    int nb1024 = (M + 1023) / 1024;

    // --- graph preprocessing: CSR by destination + symmetric norm ---
    k_zero   <<<(M + 255) / 256, 256>>>(M);
    k_count  <<<(E + 255) / 256, 256>>>(col, E);
    k_dis    <<<(M + 255) / 256, 256>>>(M);
    k_scan1  <<<nb1024, 1024>>>(M);
    k_scan2  <<<1, 32>>>(nb1024);
    k_scan3  <<<(M + 255) / 256, 256>>>(M);
    k_scatter<<<(E + 255) / 256, 256>>>(row, col, E);

    int aggBlocks = (M + 7) / 8;
    int gemmBlocks = (M + 127) / 128;

    // --- layer 1: 256 -> 128, relu ---
    k_gemm_tc<H1C, IN_C><<<gemmBlocks, 256>>>(x, W1, gh, M);
    k_agg<H1C, true><<<aggBlocks, 256>>>(gh, b1, ga);

    // --- layer 2: 128 -> 64, relu ---
    k_gemm_tc<H2C, H1C><<<gemmBlocks, 256>>>(ga, W2, gh, M);
    k_agg<H2C, true><<<aggBlocks, 256>>>(gh, b2, ga);

    // --- layer 3: 64 -> 32, no relu ---
    k_gemm_tc<OUTC, H2C><<<gemmBlocks, 256>>>(ga, W3, gh, M);
    k_agg<OUTC, false><<<aggBlocks, 256>>>(gh, b3, out);
}

// round 5
// speedup vs baseline: 1.2026x; 1.0529x over previous
#include <cuda_runtime.h>
#include <cuda_fp16.h>

// ---------------------------------------------------------------------------
// 3-layer GCN. R4 = R3 resubmit (infra failure last round, kernel untested):
// transformed features h stored fp16 (GEMM epilogue converts), halving the
// L2 gather traffic of the aggregation passes. Accumulation stays fp32;
// layer outputs (GEMM A operands, final out) stay fp32.
// ---------------------------------------------------------------------------

#define NN 100000
#define NE 1600000
#define IN_C 256
#define H1C 128
#define H2C 64
#define OUTC 32

__device__ int    g_cnt[NN];
__device__ int    g_cursor[NN];
__device__ int    g_off[NN];
__device__ int    g_bsum[128];
__device__ int    g_boff[128];
__device__ float  g_dis[NN];
__device__ int    g_esrc[NE];
__device__ float  g_enorm[NE];
__device__ __half g_h[(size_t)NN * 128];   // transformed features, fp16
__device__ float4 g_a4[(size_t)NN * 32];   // aggregated features, fp32

// ---------------------------------------------------------------------------
// graph preprocessing
// ---------------------------------------------------------------------------
__global__ void k_zero(int n) {
    int i = blockIdx.x * blockDim.x + threadIdx.x;
    if (i < n) { g_cnt[i] = 0; g_cursor[i] = 0; }
}

__global__ void k_count(const int* __restrict__ col, int e_cnt) {
    int e = blockIdx.x * blockDim.x + threadIdx.x;
    if (e < e_cnt) atomicAdd(&g_cnt[col[e]], 1);
}

__global__ void k_dis(int n) {
    int i = blockIdx.x * blockDim.x + threadIdx.x;
    if (i < n) g_dis[i] = rsqrtf((float)g_cnt[i] + 1.0f);
}

__global__ void k_scan1(int n) {
    __shared__ int s[1024];
    int i = blockIdx.x * 1024 + threadIdx.x;
    int v = (i < n) ? g_cnt[i] : 0;
    s[threadIdx.x] = v;
    __syncthreads();
    #pragma unroll
    for (int off = 1; off < 1024; off <<= 1) {
        int t = (threadIdx.x >= off) ? s[threadIdx.x - off] : 0;
        __syncthreads();
        s[threadIdx.x] += t;
        __syncthreads();
    }
    if (i < n) g_off[i] = s[threadIdx.x];
    if (threadIdx.x == 1023) g_bsum[blockIdx.x] = s[1023];
}

__global__ void k_scan2(int nb) {
    if (blockIdx.x == 0 && threadIdx.x == 0) {
        int run = 0;
        for (int b = 0; b < nb; b++) { g_boff[b] = run; run += g_bsum[b]; }
    }
}

__global__ void k_scan3(int n) {
    int i = blockIdx.x * blockDim.x + threadIdx.x;
    if (i < n) g_off[i] = g_off[i] - g_cnt[i] + g_boff[i >> 10];
}

__global__ void k_scatter(const int* __restrict__ row, const int* __restrict__ col, int e_cnt) {
    int e = blockIdx.x * blockDim.x + threadIdx.x;
    if (e >= e_cnt) return;
    int r = row[e], c = col[e];
    int pos = g_off[c] + atomicAdd(&g_cursor[c], 1);
    g_esrc[pos]  = r;
    g_enorm[pos] = g_dis[r] * g_dis[c];
}

// ---------------------------------------------------------------------------
// tensor-core GEMM: C[M,N] = A[M,K] @ W[K,N]  (tf32 3x-split), fp16 output
// ---------------------------------------------------------------------------
__device__ __forceinline__ unsigned f2tf(float f) {
    unsigned r;
    asm("cvt.rna.tf32.f32 %0, %1;" : "=r"(r) : "f"(f));
    return r;
}

__device__ __forceinline__ void mma_tf32(float* c, const unsigned* a, const unsigned* b) {
    asm volatile(
        "mma.sync.aligned.m16n8k8.row.col.f32.tf32.tf32.f32 "
        "{%0,%1,%2,%3},{%4,%5,%6,%7},{%8,%9},{%0,%1,%2,%3};"
        : "+f"(c[0]), "+f"(c[1]), "+f"(c[2]), "+f"(c[3])
        : "r"(a[0]), "r"(a[1]), "r"(a[2]), "r"(a[3]), "r"(b[0]), "r"(b[1]));
}

template <int N, int K>
__launch_bounds__(256)
__global__ void k_gemm_tc(const float* __restrict__ A, const float* __restrict__ W,
                          __half* __restrict__ C, int M) {
    constexpr int BM = 128, BK = 32;
    constexpr int WARPS_M = 4, WARPS_N = 2;
    constexpr int WM = BM / WARPS_M;   // 32
    constexpr int WN = N / WARPS_N;    // 64 / 32 / 16
    constexpr int MT = WM / 16;        // 2
    constexpr int NT = WN / 8;         // 8 / 4 / 2
    constexpr int ASTRIDE = BK + 4;
    constexpr int BSTRIDE = N + 4;

    __shared__ float As[BM * ASTRIDE];
    __shared__ float Ws[BK * BSTRIDE];

    int tid = threadIdx.x;
    int lane = tid & 31, warp = tid >> 5;
    int wm = (warp % WARPS_M) * WM;
    int wn = (warp / WARPS_M) * WN;
    int m0 = blockIdx.x * BM;
    int g = lane >> 2, tg = lane & 3;

    float acc[MT][NT][4] = {};

    for (int k0 = 0; k0 < K; k0 += BK) {
        #pragma unroll
        for (int i = 0; i < 4; i++) {
            int idx = tid + i * 256;
            int r = idx >> 3, c4 = idx & 7;
            int m = m0 + r;
            float4 v = make_float4(0.f, 0.f, 0.f, 0.f);
            if (m < M)
                v = *reinterpret_cast<const float4*>(A + (size_t)m * K + k0 + c4 * 4);
            *reinterpret_cast<float4*>(As + r * ASTRIDE + c4 * 4) = v;
        }
        constexpr int BTOT4 = BK * N / 4;
        #pragma unroll
        for (int i = 0; i < BTOT4 / 256; i++) {
            int idx = tid + i * 256;
            int r = idx / (N / 4), c4 = idx % (N / 4);
            float4 v = *reinterpret_cast<const float4*>(W + (size_t)(k0 + r) * N + c4 * 4);
            *reinterpret_cast<float4*>(Ws + r * BSTRIDE + c4 * 4) = v;
        }
        __syncthreads();

        #pragma unroll
        for (int kk = 0; kk < BK; kk += 8) {
            unsigned ahi[MT][4], alo[MT][4];
            #pragma unroll
            for (int mt = 0; mt < MT; mt++) {
                #pragma unroll
                for (int j = 0; j < 4; j++) {
                    int row = wm + mt * 16 + g + (j & 1) * 8;
                    int col = kk + tg + (j >> 1) * 4;
                    float a = As[row * ASTRIDE + col];
                    unsigned h = f2tf(a);
                    ahi[mt][j] = h;
                    alo[mt][j] = f2tf(a - __uint_as_float(h));
                }
            }
            #pragma unroll
            for (int nt = 0; nt < NT; nt++) {
                unsigned bhi[2], blo[2];
                #pragma unroll
                for (int j = 0; j < 2; j++) {
                    int kr = kk + tg + j * 4;
                    int col = wn + nt * 8 + g;
                    float b = Ws[kr * BSTRIDE + col];
                    unsigned h = f2tf(b);
                    bhi[j] = h;
                    blo[j] = f2tf(b - __uint_as_float(h));
                }
                #pragma unroll
                for (int mt = 0; mt < MT; mt++) {
                    mma_tf32(acc[mt][nt], ahi[mt], bhi);
                    mma_tf32(acc[mt][nt], ahi[mt], blo);
                    mma_tf32(acc[mt][nt], alo[mt], bhi);
                }
            }
        }
        __syncthreads();
    }

    // store fp16: c0,c1 at (row, 2tg), c2,c3 at (row+8, 2tg)
    #pragma unroll
    for (int mt = 0; mt < MT; mt++) {
        #pragma unroll
        for (int nt = 0; nt < NT; nt++) {
            int row0 = m0 + wm + mt * 16 + g;
            int col = wn + nt * 8 + 2 * tg;
            if (row0 < M)
                *reinterpret_cast<__half2*>(C + (size_t)row0 * N + col) =
                    __floats2half2_rn(acc[mt][nt][0], acc[mt][nt][1]);
            int row1 = row0 + 8;
            if (row1 < M)
                *reinterpret_cast<__half2*>(C + (size_t)row1 * N + col) =
                    __floats2half2_rn(acc[mt][nt][2], acc[mt][nt][3]);
        }
    }
}

// ---------------------------------------------------------------------------
// aggregation: warp per node; gathers fp16 rows, accumulates fp32
// ---------------------------------------------------------------------------
template <int VEC>
__device__ __forceinline__ void loadh(float* d, const __half* __restrict__ p) {
    if constexpr (VEC == 4) {
        uint2 raw = __ldg(reinterpret_cast<const uint2*>(p));
        float2 a = __half22float2(*reinterpret_cast<const __half2*>(&raw.x));
        float2 b = __half22float2(*reinterpret_cast<const __half2*>(&raw.y));
        d[0] = a.x; d[1] = a.y; d[2] = b.x; d[3] = b.y;
    } else if constexpr (VEC == 2) {
        __half2 h2 = __ldg(reinterpret_cast<const __half2*>(p));
        float2 a = __half22float2(h2);
        d[0] = a.x; d[1] = a.y;
    } else {
        d[0] = __half2float(__ldg(p));
    }
}

template <int F, bool RELU>
__launch_bounds__(256)
__global__ void k_agg(const __half* __restrict__ h, const float* __restrict__ bias,
                      float* __restrict__ out) {
    constexpr int VEC = F / 32;
    int node = (blockIdx.x * blockDim.x + threadIdx.x) >> 5;
    int lane = threadIdx.x & 31;
    if (node >= NN) return;

    float acc[VEC];
    {
        float d = g_dis[node];
        float ns = d * d;
        float t[VEC];
        loadh<VEC>(t, h + (size_t)node * F + lane * VEC);
        #pragma unroll
        for (int v = 0; v < VEC; v++) acc[v] = ns * t[v];
    }

    int start = g_off[node];
    int cnt   = g_cnt[node];
    int e = start, end = start + cnt;

    for (; e + 4 <= end; e += 4) {
        int   s0 = g_esrc[e],   s1 = g_esrc[e + 1],   s2 = g_esrc[e + 2],   s3 = g_esrc[e + 3];
        float n0 = g_enorm[e],  n1 = g_enorm[e + 1],  n2 = g_enorm[e + 2],  n3 = g_enorm[e + 3];
        float t0[VEC], t1[VEC], t2[VEC], t3[VEC];
        loadh<VEC>(t0, h + (size_t)s0 * F + lane * VEC);
        loadh<VEC>(t1, h + (size_t)s1 * F + lane * VEC);
        loadh<VEC>(t2, h + (size_t)s2 * F + lane * VEC);
        loadh<VEC>(t3, h + (size_t)s3 * F + lane * VEC);
        #pragma unroll
        for (int v = 0; v < VEC; v++) {
            acc[v] += n0 * t0[v];
            acc[v] += n1 * t1[v];
            acc[v] += n2 * t2[v];
            acc[v] += n3 * t3[v];
        }
    }
    for (; e < end; e++) {
        int s = g_esrc[e];
        float nm = g_enorm[e];
        float t[VEC];
        loadh<VEC>(t, h + (size_t)s * F + lane * VEC);
        #pragma unroll
        for (int v = 0; v < VEC; v++) acc[v] += nm * t[v];
    }

    float res[VEC];
    #pragma unroll
    for (int v = 0; v < VEC; v++) {
        float r = acc[v] + bias[lane * VEC + v];
        if (RELU) r = fmaxf(r, 0.0f);
        res[v] = r;
    }
    float* op = out + (size_t)node * F + lane * VEC;
    if constexpr (VEC == 4)      *reinterpret_cast<float4*>(op) = make_float4(res[0], res[1], res[2], res[3]);
    else if constexpr (VEC == 2) *reinterpret_cast<float2*>(op) = make_float2(res[0], res[1]);
    else                         *op = res[0];
}

// ---------------------------------------------------------------------------
extern "C" void kernel_launch(void* const* d_in, const int* in_sizes, int n_in,
                              void* d_out, int out_size) {
    const float* x  = (const float*)d_in[0];
    const int*   ei = (const int*)d_in[1];
    const float* W1 = (const float*)d_in[2];
    const float* b1 = (const float*)d_in[3];
    const float* W2 = (const float*)d_in[4];
    const float* b2 = (const float*)d_in[5];
    const float* W3 = (const float*)d_in[6];
    const float* b3 = (const float*)d_in[7];

    int M = in_sizes[0] / IN_C;   // 100000
    int E = in_sizes[1] / 2;      // 1600000
    const int* row = ei;          // sources
    const int* col = ei + E;      // targets
    float* out = (float*)d_out;

    __half* gh;
    float*  ga;
    cudaGetSymbolAddress((void**)&gh, g_h);
    cudaGetSymbolAddress((void**)&ga, g_a4);

    int nb1024 = (M + 1023) / 1024;

    // --- graph preprocessing: CSR by destination + symmetric norm ---
    k_zero   <<<(M + 255) / 256, 256>>>(M);
    k_count  <<<(E + 255) / 256, 256>>>(col, E);
    k_dis    <<<(M + 255) / 256, 256>>>(M);
    k_scan1  <<<nb1024, 1024>>>(M);
    k_scan2  <<<1, 32>>>(nb1024);
    k_scan3  <<<(M + 255) / 256, 256>>>(M);
    k_scatter<<<(E + 255) / 256, 256>>>(row, col, E);

    int aggBlocks = (M + 7) / 8;
    int gemmBlocks = (M + 127) / 128;

    // --- layer 1: 256 -> 128, relu ---
    k_gemm_tc<H1C, IN_C><<<gemmBlocks, 256>>>(x, W1, gh, M);
    k_agg<H1C, true><<<aggBlocks, 256>>>(gh, b1, ga);

    // --- layer 2: 128 -> 64, relu ---
    k_gemm_tc<H2C, H1C><<<gemmBlocks, 256>>>(ga, W2, gh, M);
    k_agg<H2C, true><<<aggBlocks, 256>>>(gh, b2, ga);

    // --- layer 3: 64 -> 32, no relu ---
    k_gemm_tc<OUTC, H2C><<<gemmBlocks, 256>>>(ga, W3, gh, M);
    k_agg<OUTC, false><<<aggBlocks, 256>>>(gh, b3, out);
}